// round 2
// baseline (speedup 1.0000x reference)
#include <cuda_runtime.h>
#include <cmath>

// Fully-fused Swin block, round 2: LDS-vectorized GEMMs (float4 activations),
// full-lane 96-column tiles (col = lane + j*32), K stored transposed for
// conflict-free QK^T. One block per 7x7 window, 256 threads, 2 blocks/SM.

namespace {

constexpr int WSZ   = 7;
constexpr int NTOK  = 49;
constexpr int NPAD  = 56;
constexpr int CDIM  = 96;
constexpr int NHEAD = 3;
constexpr int HDIM  = 32;
constexpr int IMG   = 224;
constexpr int P     = 100;    // row pitch (multiple of 4 -> float4 rows)
constexpr int KTP   = 57;     // K^T pitch (odd -> conflict-free strided access)
constexpr int SHIFT_SZ = 3;
constexpr int ROW   = NPAD * P;                 // 5600 floats per buffer
constexpr int SMEM_FLOATS = 4 * ROW + 512;
constexpr int SMEM_BYTES  = SMEM_FLOATS * 4;    // ~91.6 KB -> 2 blocks/SM

__device__ __forceinline__ float gelu_exact(float v) {
    return 0.5f * v * (1.f + erff(v * 0.70710678118654752f));
}

// 96-output-column GEMM tile: 7 tokens (warp-private rows) x 3 cols/lane.
// src rows at pitch P, float4-aligned. Weights row-major [k][ldw].
// MODE 0: row-major store dst[(n0+t)*P + cc]
// MODE 1: transposed store dst[cc*KTP + (n0+t)]
template<int KDIM, int MODE, bool GELU>
__device__ __forceinline__ void gemm96(
    const float* __restrict__ src, int n0,
    const float* __restrict__ w, int ldw, int colOff,
    const float* __restrict__ bias, float scale,
    float* __restrict__ dst, int lane)
{
    const int c0 = colOff + lane;
    float acc[7][3];
    #pragma unroll
    for (int t = 0; t < 7; t++) { acc[t][0] = 0.f; acc[t][1] = 0.f; acc[t][2] = 0.f; }

    const float* wp = w + c0;
    #pragma unroll 1
    for (int k4 = 0; k4 < KDIM; k4 += 4) {
        float wr[4][3];
        #pragma unroll
        for (int kk = 0; kk < 4; kk++) {
            const float* wrow = wp + (k4 + kk) * ldw;
            wr[kk][0] = wrow[0];
            wr[kk][1] = wrow[32];
            wr[kk][2] = wrow[64];
        }
        float xv[7][4];
        #pragma unroll
        for (int t = 0; t < 7; t++) {
            float4 v = *reinterpret_cast<const float4*>(src + (n0 + t) * P + k4);
            xv[t][0] = v.x; xv[t][1] = v.y; xv[t][2] = v.z; xv[t][3] = v.w;
        }
        #pragma unroll
        for (int kk = 0; kk < 4; kk++) {
            #pragma unroll
            for (int t = 0; t < 7; t++) {
                float xs = xv[t][kk];
                acc[t][0] = fmaf(xs, wr[kk][0], acc[t][0]);
                acc[t][1] = fmaf(xs, wr[kk][1], acc[t][1]);
                acc[t][2] = fmaf(xs, wr[kk][2], acc[t][2]);
            }
        }
    }
    float bb[3] = { bias[c0], bias[c0 + 32], bias[c0 + 64] };
    #pragma unroll
    for (int j = 0; j < 3; j++) {
        const int cc = lane + j * 32;   // column within the 96-wide output
        #pragma unroll
        for (int t = 0; t < 7; t++) {
            float v = (acc[t][j] + bb[j]) * scale;
            if (GELU) v = gelu_exact(v);
            if (MODE == 0) dst[(n0 + t) * P + cc] = v;
            else           dst[cc * KTP + (n0 + t)] = v;
        }
    }
}

// Accumulating variant (for fc2 chunks): adds into oacc[7][3], no store.
template<int KDIM>
__device__ __forceinline__ void gemm96_acc(
    const float* __restrict__ src, int n0,
    const float* __restrict__ w, int ldw, int lane,
    float oacc[7][3])
{
    const float* wp = w + lane;
    #pragma unroll 1
    for (int k4 = 0; k4 < KDIM; k4 += 4) {
        float wr[4][3];
        #pragma unroll
        for (int kk = 0; kk < 4; kk++) {
            const float* wrow = wp + (k4 + kk) * ldw;
            wr[kk][0] = wrow[0];
            wr[kk][1] = wrow[32];
            wr[kk][2] = wrow[64];
        }
        float xv[7][4];
        #pragma unroll
        for (int t = 0; t < 7; t++) {
            float4 v = *reinterpret_cast<const float4*>(src + (n0 + t) * P + k4);
            xv[t][0] = v.x; xv[t][1] = v.y; xv[t][2] = v.z; xv[t][3] = v.w;
        }
        #pragma unroll
        for (int kk = 0; kk < 4; kk++) {
            #pragma unroll
            for (int t = 0; t < 7; t++) {
                float xs = xv[t][kk];
                oacc[t][0] = fmaf(xs, wr[kk][0], oacc[t][0]);
                oacc[t][1] = fmaf(xs, wr[kk][1], oacc[t][1]);
                oacc[t][2] = fmaf(xs, wr[kk][2], oacc[t][2]);
            }
        }
    }
}

__global__ void __launch_bounds__(256, 2) swin_fused(
    const float* __restrict__ x,
    const float* __restrict__ qkv_w,
    const float* __restrict__ qkv_b,
    const float* __restrict__ proj_w,
    const float* __restrict__ proj_b,
    const float* __restrict__ rpb,
    const float* __restrict__ n2g,
    const float* __restrict__ n2b,
    const float* __restrict__ fc1_w,
    const float* __restrict__ fc1_b,
    const float* __restrict__ fc2_w,
    const float* __restrict__ fc2_b,
    float* __restrict__ out)
{
    extern __shared__ float sm[];
    float* sX   = sm;             // X tile -> attention output
    float* sQ   = sm + ROW;       // Q (row-major) -> xr (proj out, residual)
    float* sKT  = sm + 2 * ROW;   // K^T (pitch 57) -> LayerNorm out (row-major)
    float* sV   = sm + 3 * ROW;   // V (row-major) -> gelu(fc1) chunk
    float* sRpb = sm + 4 * ROW;

    const int tid  = threadIdx.x;
    const int warp = tid >> 5;
    const int lane = tid & 31;

    const int wid = blockIdx.x;
    const int b   = wid >> 10;
    const int wy  = (wid >> 5) & 31;
    const int wx  = wid & 31;
    const int hs0 = wy * WSZ;
    const int ws0 = wx * WSZ;

    for (int i = tid; i < 507; i += 256) sRpb[i] = rpb[i];

    // ---- load window tile (cyclic shift = rolled index) ----
    for (int i = tid; i < NPAD * CDIM; i += 256) {
        int r = i / CDIM, c = i - (i / CDIM) * CDIM;
        float v = 0.f;
        if (r < NTOK) {
            int ty = r / WSZ, tx = r - (r / WSZ) * WSZ;
            int h = hs0 + ty + SHIFT_SZ; if (h >= IMG) h -= IMG;
            int w = ws0 + tx + SHIFT_SZ; if (w >= IMG) w -= IMG;
            v = x[(((size_t)b * IMG + h) * IMG + w) * CDIM + c];
        }
        sX[r * P + c] = v;
    }
    // zero the pitch padding so float4 loads of cols 96..99 are defined
    for (int r = tid; r < NPAD; r += 256) {
        sX[r * P + 96] = 0.f; sX[r * P + 97] = 0.f;
        sX[r * P + 98] = 0.f; sX[r * P + 99] = 0.f;
    }
    __syncthreads();

    const int n0 = warp * 7;

    // ================= QKV: three 96-col passes =================
    gemm96<96, 0, false>(sX, n0, qkv_w, 288,   0, qkv_b,
                         0.17677669529663687f, sQ, lane);   // Q (pre-scaled)
    gemm96<96, 1, false>(sX, n0, qkv_w, 288,  96, qkv_b, 1.f, sKT, lane); // K^T
    gemm96<96, 0, false>(sX, n0, qkv_w, 288, 192, qkv_b, 1.f, sV,  lane); // V
    __syncthreads();

    // ================= attention: one (head,row) per warp-task =================
    for (int task = warp; task < NHEAD * NTOK; task += 8) {
        const int h    = task / NTOK;
        const int i    = task - h * NTOK;
        const int base = h * HDIM;
        const bool v2  = (lane < 17);
        const int j2   = v2 ? lane + 32 : lane;

        float s1 = 0.f, s2 = 0.f;
        const float* qr = sQ + i * P + base;
        const float* kt = sKT + base * KTP;
        #pragma unroll
        for (int d4 = 0; d4 < HDIM; d4 += 4) {
            float4 q4 = *reinterpret_cast<const float4*>(qr + d4);
            float qv[4] = { q4.x, q4.y, q4.z, q4.w };
            #pragma unroll
            for (int kk = 0; kk < 4; kk++) {
                const float* krow = kt + (d4 + kk) * KTP;
                s1 = fmaf(qv[kk], krow[lane], s1);
                s2 = fmaf(qv[kk], krow[j2],   s2);
            }
        }
        const int yi = i / WSZ, xi = i - (i / WSZ) * WSZ;
        {
            int yj = lane / WSZ, xj = lane - (lane / WSZ) * WSZ;
            s1 += sRpb[((yi - yj + 6) * 13 + (xi - xj + 6)) * NHEAD + h];
        }
        if (v2) {
            int yj = j2 / WSZ, xj = j2 - (j2 / WSZ) * WSZ;
            s2 += sRpb[((yi - yj + 6) * 13 + (xi - xj + 6)) * NHEAD + h];
        } else {
            s2 = -1e30f;
        }
        float mx = fmaxf(s1, s2);
        #pragma unroll
        for (int o = 16; o > 0; o >>= 1)
            mx = fmaxf(mx, __shfl_xor_sync(0xffffffffu, mx, o));
        float e1 = __expf(s1 - mx);
        float e2 = v2 ? __expf(s2 - mx) : 0.f;
        float sum = e1 + e2;
        #pragma unroll
        for (int o = 16; o > 0; o >>= 1)
            sum += __shfl_xor_sync(0xffffffffu, sum, o);
        float inv = 1.f / sum;
        float p1 = e1 * inv, p2 = e2 * inv;

        float acc = 0.f;
        const float* vc = sV + base + lane;   // lane = output dim d (conflict-free)
        #pragma unroll
        for (int j = 0; j < 32; j++) {
            float p = __shfl_sync(0xffffffffu, p1, j);
            acc = fmaf(p, vc[j * P], acc);
        }
        #pragma unroll
        for (int j = 0; j < 17; j++) {
            float p = __shfl_sync(0xffffffffu, p2, j);
            acc = fmaf(p, vc[(j + 32) * P], acc);
        }
        sX[i * P + base + lane] = acc;   // attention output
    }
    __syncthreads();
    // Pad rows 49..55 of sX still hold X values (finite) -> downstream math is
    // garbage-but-finite there and never stored. All later phases are
    // warp-private per row, so warp syncs suffice.

    // ================= proj: AO(sX) -> xr(sQ) =================
    gemm96<96, 0, false>(sX, n0, proj_w, 96, 0, proj_b, 1.f, sQ, lane);
    __syncwarp();

    // ================= LayerNorm: xr(sQ) -> sKT region (row-major) =============
    float* sLN = sKT;
    {
        const float g0 = n2g[lane], g1 = n2g[lane + 32], g2 = n2g[lane + 64];
        const float b0 = n2b[lane], b1 = n2b[lane + 32], b2 = n2b[lane + 64];
        #pragma unroll
        for (int t = 0; t < 7; t++) {
            const float* row = sQ + (n0 + t) * P;
            float v0 = row[lane], v1 = row[lane + 32], v2r = row[lane + 64];
            float s  = v0 + v1 + v2r;
            float sq = v0 * v0 + v1 * v1 + v2r * v2r;
            #pragma unroll
            for (int o = 16; o > 0; o >>= 1) {
                s  += __shfl_xor_sync(0xffffffffu, s, o);
                sq += __shfl_xor_sync(0xffffffffu, sq, o);
            }
            float mu   = s * (1.f / 96.f);
            float var  = sq * (1.f / 96.f) - mu * mu;
            float rstd = rsqrtf(var + 1e-5f);
            float* nr = sLN + (n0 + t) * P;
            nr[lane]      = (v0  - mu) * rstd * g0 + b0;
            nr[lane + 32] = (v1  - mu) * rstd * g1 + b1;
            nr[lane + 64] = (v2r - mu) * rstd * g2 + b2;
            // pad cols for float4 reads
            if (lane < 4) nr[96 + lane] = 0.f;
        }
    }
    __syncwarp();

    // ================= MLP: 4 hidden chunks of 96 =================
    float oacc[7][3];
    #pragma unroll
    for (int t = 0; t < 7; t++) { oacc[t][0] = 0.f; oacc[t][1] = 0.f; oacc[t][2] = 0.f; }

    #pragma unroll 1
    for (int chunk = 0; chunk < 4; chunk++) {
        const int hb = chunk * 96;
        gemm96<96, 0, true>(sLN, n0, fc1_w, 384, hb, fc1_b, 1.f, sV, lane);
        __syncwarp();
        gemm96_acc<96>(sV, n0, fc2_w + (size_t)hb * CDIM, CDIM, lane, oacc);
        __syncwarp();
    }

    // ================= epilogue: residual + reverse shift + store ===============
    {
        const float fb0 = fc2_b[lane], fb1 = fc2_b[lane + 32], fb2 = fc2_b[lane + 64];
        #pragma unroll
        for (int t = 0; t < 7; t++) {
            int n = n0 + t;
            if (n < NTOK) {
                int ty = n / WSZ, tx = n - (n / WSZ) * WSZ;
                int h = hs0 + ty + SHIFT_SZ; if (h >= IMG) h -= IMG;
                int w = ws0 + tx + SHIFT_SZ; if (w >= IMG) w -= IMG;
                const float* res = sQ + n * P;
                float* op = out + (((size_t)b * IMG + h) * IMG + w) * CDIM;
                op[lane]      = res[lane]      + oacc[t][0] + fb0;
                op[lane + 32] = res[lane + 32] + oacc[t][1] + fb1;
                op[lane + 64] = res[lane + 64] + oacc[t][2] + fb2;
            }
        }
    }
}

} // namespace

extern "C" void kernel_launch(void* const* d_in, const int* in_sizes, int n_in,
                              void* d_out, int out_size) {
    (void)in_sizes; (void)n_in; (void)out_size;
    cudaFuncSetAttribute(swin_fused, cudaFuncAttributeMaxDynamicSharedMemorySize,
                         SMEM_BYTES);
    swin_fused<<<8 * 32 * 32, 256, SMEM_BYTES>>>(
        (const float*)d_in[0],  (const float*)d_in[1],  (const float*)d_in[2],
        (const float*)d_in[3],  (const float*)d_in[4],  (const float*)d_in[5],
        (const float*)d_in[6],  (const float*)d_in[7],  (const float*)d_in[8],
        (const float*)d_in[9],  (const float*)d_in[10], (const float*)d_in[11],
        (float*)d_out);
}